// round 13
// baseline (speedup 1.0000x reference)
#include <cuda_runtime.h>
#include <cuda_pipeline.h>
#include <math.h>
#include <float.h>

#define NN 256
#define ECAP 4608
#define DMAX 16
#define RSTRIDE 130            // padded row stride (floats) in staging buffers
#define WROWS (65 * RSTRIDE)   // 64 src rows + 1 xr row
#define WBUF (WROWS + 64)      // + 64-float edge-weight strip, per warp
#define KA_WARPS 5

// ---------------- scratch ----------------
__device__ __align__(16) float d_xl0[NN * 128];
__device__ __align__(16) float d_xr0[NN * 128];
__device__ __align__(16) float d_xlM[NN * 128];
__device__ __align__(16) float d_xrM[NN * 128];
__device__ __align__(16) float d_xl20[NN * 128];
__device__ __align__(16) float d_xl2d[NN * DMAX * 128];
__device__ __align__(16) float d_xr2[NN * 128];
__device__ int   d_rowptr[NN + 1];
__device__ int   d_csrc[ECAP];
__device__ int   d_colptr[NN + 1];
__device__ int   d_cdst[ECAP];
__device__ int   d_dlist[NN * DMAX];
__device__ int   d_nd[NN];
__device__ int   d_dtasks[NN * DMAX];
__device__ int   d_ntask;

__device__ __forceinline__ float warp_sum(float v) {
    v += __shfl_xor_sync(0xffffffffu, v, 16);
    v += __shfl_xor_sync(0xffffffffu, v, 8);
    v += __shfl_xor_sync(0xffffffffu, v, 4);
    v += __shfl_xor_sync(0xffffffffu, v, 2);
    v += __shfl_xor_sync(0xffffffffu, v, 1);
    return v;
}
__device__ __forceinline__ float warp_max(float v) {
    v = fmaxf(v, __shfl_xor_sync(0xffffffffu, v, 16));
    v = fmaxf(v, __shfl_xor_sync(0xffffffffu, v, 8));
    v = fmaxf(v, __shfl_xor_sync(0xffffffffu, v, 4));
    v = fmaxf(v, __shfl_xor_sync(0xffffffffu, v, 2));
    v = fmaxf(v, __shfl_xor_sync(0xffffffffu, v, 1));
    return v;
}

// GAT softmax for one (target, head) from a staged smem buffer.
__device__ __forceinline__ float2 gat_head_smem(
    const float* __restrict__ wb, int deg,
    const float* __restrict__ satt, int hoff, int lane, float* __restrict__ wsm)
{
    int c0 = 2 * lane;
    const float* xrp = wb + 64 * RSTRIDE + hoff;
    float lg1 = -1e30f, lg2 = -1e30f;
    if (lane < deg) {
        const float* r = wb + lane * RSTRIDE + hoff;
        float acc = 0.f;
        #pragma unroll
        for (int c = 0; c < 64; c += 2) {
            float vx = r[c], vy = r[c + 1];
            float t0 = vx + xrp[c];     t0 = t0 > 0.f ? t0 : 0.2f * t0;
            float t1 = vy + xrp[c + 1]; t1 = t1 > 0.f ? t1 : 0.2f * t1;
            acc += satt[hoff + c] * t0 + satt[hoff + c + 1] * t1;
        }
        lg1 = acc;
    }
    if (32 + lane < deg) {
        const float* r = wb + (32 + lane) * RSTRIDE + hoff;
        float acc = 0.f;
        #pragma unroll
        for (int c = 0; c < 64; c += 2) {
            float vx = r[c], vy = r[c + 1];
            float t0 = vx + xrp[c];     t0 = t0 > 0.f ? t0 : 0.2f * t0;
            float t1 = vy + xrp[c + 1]; t1 = t1 > 0.f ? t1 : 0.2f * t1;
            acc += satt[hoff + c] * t0 + satt[hoff + c + 1] * t1;
        }
        lg2 = acc;
    }
    float m = warp_max(fmaxf(lg1, lg2));
    float w1 = (lane < deg)      ? __expf(lg1 - m) : 0.f;
    float w2 = (32 + lane < deg) ? __expf(lg2 - m) : 0.f;
    float denom = warp_sum(w1 + w2);

    wsm[lane] = w1;
    wsm[32 + lane] = w2;
    __syncwarp();

    float ax = 0.f, ay = 0.f;
    #pragma unroll 4
    for (int j = 0; j < deg; j++) {
        float wj = wsm[j];
        float2 v = *(const float2*)(wb + j * RSTRIDE + hoff + c0);
        ax += wj * v.x; ay += wj * v.y;
    }
    __syncwarp();
    float inv = 1.f / (denom + 1e-16f);
    return make_float2(ax * inv, ay * inv);
}

// ---------------- async staging helper (cp.async, 16B granules) --------------
__device__ __forceinline__ void stage_async(const float* __restrict__ g, float* s, int n, int tid) {
    const float4* g4 = (const float4*)g;
    float4* s4 = (float4*)s;
    for (int idx = tid; idx < (n >> 2); idx += 256)
        __pipeline_memcpy_async(s4 + idx, g4 + idx, 16);
}

// ---------------- K1: fused precompute, 4 rows/CTA, 3 staging phases ----------
__global__ void __launch_bounds__(256) k1_precompute(
    const float* __restrict__ x, const float* __restrict__ E_emb,
    const float* __restrict__ node_proj, const float* __restrict__ emb_proj,
    const float* __restrict__ conv_w0, const float* __restrict__ conv_w1,
    const float* __restrict__ conv_b,
    const float* __restrict__ lin2_w, const float* __restrict__ lin2_b,
    const float* __restrict__ masked_proj, const float* __restrict__ normal_proj,
    const float* __restrict__ g1_wl, const float* __restrict__ g1_bl,
    const float* __restrict__ g1_wr, const float* __restrict__ g1_br)
{
    extern __shared__ __align__(16) float smem[];
    float* sW   = smem;           // 32768
    float* sx   = sW + 32768;
    float* sE   = sx + 256;
    float* sxp  = sE + 256;
    float* sEp  = sxp + 512;
    float* sh0  = sEp + 512;
    float* shM  = sh0 + 512;
    float* sm0  = shM + 512;
    float* smM  = sm0 + 256;
    float* sp0  = smM + 256;
    float* spM  = sp0 + 256;
    float* sTmp = spM + 256;      // 1024

    int tid = threadIdx.x;
    int r0 = blockIdx.x * 4;

    stage_async(node_proj, sW, 8192, tid);
    stage_async(emb_proj,  sW + 8192, 8192, tid);
    __pipeline_commit();

    sx[tid] = x[r0 * 64 + tid];
    sE[tid] = E_emb[r0 * 64 + tid];

    __pipeline_wait_prior(0);
    __syncthreads();
    {
        int half = tid >> 7, c = tid & 127;
        const float* W = sW + half * 8192;
        const float* in = half ? sE : sx;
        float a0 = 0.f, a1 = 0.f, a2 = 0.f, a3 = 0.f;
        #pragma unroll 8
        for (int k = 0; k < 64; k++) {
            float w = W[k * 128 + c];
            a0 += in[k] * w; a1 += in[64 + k] * w;
            a2 += in[128 + k] * w; a3 += in[192 + k] * w;
        }
        float* o = half ? sEp : sxp;
        o[c] = a0; o[128 + c] = a1; o[256 + c] = a2; o[384 + c] = a3;
    }
    __syncthreads();

    stage_async(conv_w1, sW, 16384, tid);
    stage_async(conv_w0, sW + 16384, 16384, tid);
    __pipeline_commit();
    __pipeline_wait_prior(0);
    __syncthreads();
    {
        int half = tid >> 7, c = tid & 127;
        const float* W = sW + half * 16384;
        const float* in = half ? sEp : sxp;
        float a0 = 0.f, a1 = 0.f, a2 = 0.f, a3 = 0.f;
        #pragma unroll 8
        for (int k = 0; k < 128; k++) {
            float w = W[k * 128 + c];
            a0 += in[k] * w; a1 += in[128 + k] * w;
            a2 += in[256 + k] * w; a3 += in[384 + k] * w;
        }
        float* o = sTmp + half * 512;
        o[c] = a0; o[128 + c] = a1; o[256 + c] = a2; o[384 + c] = a3;
    }
    __syncthreads();
    stage_async(lin2_w,      sW, 8192, tid);
    stage_async(normal_proj, sW + 8192, 4096, tid);
    stage_async(masked_proj, sW + 12288, 4096, tid);
    stage_async(g1_wl,       sW + 16384, 8192, tid);
    stage_async(g1_wr,       sW + 24576, 8192, tid);
    __pipeline_commit();

    if (tid < 128) {
        float cb = conv_b[tid];
        #pragma unroll
        for (int r = 0; r < 4; r++) {
            float xw1 = sTmp[r * 128 + tid];
            float bM  = sTmp[512 + r * 128 + tid] + cb;
            sh0[r * 128 + tid] = tanhf(bM + xw1);
            shM[r * 128 + tid] = tanhf(bM);
        }
    }
    __pipeline_wait_prior(0);
    __syncthreads();

    {
        int v = tid >> 7, kh = (tid >> 6) & 1, c = tid & 63;
        const float* hs = v ? shM : sh0;
        float a0 = 0.f, a1 = 0.f, a2 = 0.f, a3 = 0.f;
        #pragma unroll 8
        for (int kk = 0; kk < 64; kk++) {
            int k = kh * 64 + kk;
            float w = sW[k * 64 + c];
            a0 += hs[k] * w; a1 += hs[128 + k] * w;
            a2 += hs[256 + k] * w; a3 += hs[384 + k] * w;
        }
        float* o = sTmp + v * 512 + kh * 64;
        o[c] = a0; o[128 + c] = a1; o[256 + c] = a2; o[384 + c] = a3;
    }
    __syncthreads();
    {
        int v = tid >> 7, rp = (tid >> 6) & 1, c = tid & 63;
        float lb = lin2_b[c];
        float* d = v ? smM : sm0;
        #pragma unroll
        for (int rr = 0; rr < 2; rr++) {
            int r = rp * 2 + rr;
            d[r * 64 + c] = sTmp[v * 512 + r * 128 + c] + sTmp[v * 512 + r * 128 + 64 + c] + lb;
        }
    }
    __syncthreads();

    {
        int v = tid >> 7, rp = (tid >> 6) & 1, c = tid & 63;
        const float* s = v ? smM : sm0;
        const float* W = sW + 8192 + v * 4096;
        float* d = v ? spM : sp0;
        float a0 = 0.f, a1 = 0.f;
        int r = rp * 2;
        #pragma unroll 8
        for (int k = 0; k < 64; k++) {
            float w = W[k * 64 + c];
            a0 += s[r * 64 + k] * w; a1 += s[(r + 1) * 64 + k] * w;
        }
        d[r * 64 + c] = a0; d[(r + 1) * 64 + c] = a1;
    }
    __syncthreads();

    {
        int half = tid >> 7, c = tid & 127;
        const float* W = sW + 16384 + half * 8192;
        float b0[4] = {0.f, 0.f, 0.f, 0.f};
        float bm[4] = {0.f, 0.f, 0.f, 0.f};
        #pragma unroll 8
        for (int k = 0; k < 64; k++) {
            float w = W[k * 128 + c];
            #pragma unroll
            for (int r = 0; r < 4; r++) {
                b0[r] += sp0[r * 64 + k] * w;
                bm[r] += spM[r * 64 + k] * w;
            }
        }
        float bb = half ? g1_br[c] : g1_bl[c];
        float* o0 = half ? d_xr0 : d_xl0;
        float* oM = half ? d_xrM : d_xlM;
        #pragma unroll
        for (int r = 0; r < 4; r++) {
            o0[(r0 + r) * 128 + c] = b0[r] + bb;
            oM[(r0 + r) * 128 + c] = bm[r] + bb;
        }
    }
}

// ---------------- K2: CSR + CSC + delta lists + task compaction --------------
__global__ void __launch_bounds__(1024) k2_csr(const int* __restrict__ ei, int E)
{
    __shared__ int c1[NN], c2[NN], cur1[NN], cur2[NN];
    __shared__ int ws[16];
    __shared__ int srow[NN + 1], scol[NN + 1];
    __shared__ int scsrc[ECAP], scdst[ECAP];
    __shared__ unsigned innb[32][8], chosen[32][8];
    __shared__ int ndcnt[32];

    int tid = threadIdx.x, lane = tid & 31, w = tid >> 5;
    if (tid == 0) d_ntask = 0;
    if (tid < NN) { c1[tid] = 0; c2[tid] = 0; }
    __syncthreads();
    const int* src = ei;
    const int* dst = ei + E;
    for (int e = tid; e < E; e += 1024) {
        atomicAdd(&c1[dst[e]], 1);
        atomicAdd(&c2[src[e]], 1);
    }
    __syncthreads();
    if (tid < NN) {
        int v1 = c1[tid], v2 = c2[tid];
        int x1 = v1, x2 = v2;
        #pragma unroll
        for (int d = 1; d < 32; d <<= 1) {
            int y1 = __shfl_up_sync(0xffffffffu, x1, d);
            int y2 = __shfl_up_sync(0xffffffffu, x2, d);
            if (lane >= d) { x1 += y1; x2 += y2; }
        }
        if (lane == 31) { ws[w] = x1; ws[8 + w] = x2; }
    }
    __syncthreads();
    if (tid == 0) {
        int a = 0, b = 0;
        for (int q = 0; q < 8; q++) {
            int t1 = ws[q], t2 = ws[8 + q];
            ws[q] = a; ws[8 + q] = b;
            a += t1; b += t2;
        }
    }
    __syncthreads();
    if (tid < NN) {
        int v1 = c1[tid], v2 = c2[tid];
        int x1 = v1, x2 = v2;
        #pragma unroll
        for (int d = 1; d < 32; d <<= 1) {
            int y1 = __shfl_up_sync(0xffffffffu, x1, d);
            int y2 = __shfl_up_sync(0xffffffffu, x2, d);
            if (lane >= d) { x1 += y1; x2 += y2; }
        }
        int ex1 = ws[w] + x1 - v1;
        int ex2 = ws[8 + w] + x2 - v2;
        srow[tid] = ex1; scol[tid] = ex2;
        d_rowptr[tid] = ex1; d_colptr[tid] = ex2;
        cur1[tid] = ex1; cur2[tid] = ex2;
        if (tid == NN - 1) {
            srow[NN] = ex1 + v1; scol[NN] = ex2 + v2;
            d_rowptr[NN] = ex1 + v1; d_colptr[NN] = ex2 + v2;
        }
    }
    __syncthreads();
    for (int e = tid; e < E; e += 1024) {
        int p1 = atomicAdd(&cur1[dst[e]], 1); scsrc[p1] = src[e];
        int p2 = atomicAdd(&cur2[src[e]], 1); scdst[p2] = dst[e];
    }
    __syncthreads();
    for (int e = tid; e < E; e += 1024) {
        d_csrc[e] = scsrc[e];
        d_cdst[e] = scdst[e];
    }
    __syncthreads();

    // ---- delta lists (merged kD): warp w handles instances w*8 .. w*8+7 ----
    for (int ii = 0; ii < 8; ii++) {
        int i = w * 8 + ii;
        if (lane < 8) { innb[w][lane] = 0u; chosen[w][lane] = 0u; }
        if (lane == 0) {
            ndcnt[w] = 1;
            d_dlist[i * DMAX] = i;
        }
        __syncwarp();
        int b = srow[i], e = srow[i + 1];
        for (int p = b + lane; p < e; p += 32) {
            int s = scsrc[p];
            atomicOr(&innb[w][s >> 5], 1u << (s & 31));
        }
        __syncwarp();
        int cb = scol[i], ce = scol[i + 1];
        for (int p = cb + lane; p < ce; p += 32) {
            int t = scdst[p];
            if (t != i && ((innb[w][t >> 5] >> (t & 31)) & 1u)) {
                unsigned bit = 1u << (t & 31);
                unsigned old = atomicOr(&chosen[w][t >> 5], bit);
                if (!(old & bit)) {
                    int sl = atomicAdd(&ndcnt[w], 1);
                    if (sl < DMAX) d_dlist[i * DMAX + sl] = t;
                }
            }
        }
        __syncwarp();
        if (lane == 0) {
            int nd = min(ndcnt[w], DMAX);
            d_nd[i] = nd;
            int base = atomicAdd(&d_ntask, nd);
            for (int k = 0; k < nd; k++)
                d_dtasks[base + k] = i * DMAX + k;
        }
        __syncwarp();
    }
}

// ---------------- KA: layer-1 GAT + fused layer-2 transforms -----------------
__global__ void __launch_bounds__(KA_WARPS * 32) kA_gat1(
    const float* __restrict__ att1, const float* __restrict__ bias1,
    const float* __restrict__ w2l, const float* __restrict__ b2l,
    const float* __restrict__ w2r, const float* __restrict__ b2r)
{
    extern __shared__ __align__(16) float sbuf[];
    float* satt  = sbuf + KA_WARPS * WBUF;   // 128
    float* sbias = satt + 128;               // 64

    int tid = threadIdx.x, lane = tid & 31, wid = tid >> 5;
    if (tid < 128) satt[tid] = att1[tid];
    if (tid < 64)  sbias[tid] = bias1[tid];
    __syncthreads();

    float* wb  = sbuf + wid * WBUF;
    float* wsm = wb + WROWS;
    int c0 = 2 * lane;
    int step = gridDim.x * KA_WARPS;
    int total = NN + d_ntask;

    for (int task = blockIdx.x * KA_WARPS + wid; task < total; task += step) {
        int t, isub;
        float* xlout;
        bool do_xr = false;
        if (task < NN) {
            t = task; isub = -1;
            xlout = d_xl20 + t * 128;
        } else {
            int v = d_dtasks[task - NN];
            isub = v >> 4;           // DMAX = 16
            t = d_dlist[v];
            xlout = d_xl2d + v * 128;
            do_xr = ((v & (DMAX - 1)) == 0);
        }
        int b = d_rowptr[t], deg = d_rowptr[t + 1] - b;

        // stage source rows + xr row via cp.async
        int s1 = (lane < deg)      ? d_csrc[b + lane]      : 0;
        int s2 = (32 + lane < deg) ? d_csrc[b + 32 + lane] : 0;
        for (int j = 0; j < deg; j++) {
            int s = __shfl_sync(0xffffffffu, (j < 32) ? s1 : s2, j & 31);
            const float* src = (s == isub) ? (d_xlM + s * 128) : (d_xl0 + s * 128);
            __pipeline_memcpy_async(wb + j * RSTRIDE + c0,      src + c0,      8);
            __pipeline_memcpy_async(wb + j * RSTRIDE + 64 + c0, src + 64 + c0, 8);
        }
        {
            const float* xr = (t == isub) ? (d_xrM + t * 128) : (d_xr0 + t * 128);
            __pipeline_memcpy_async(wb + 64 * RSTRIDE + c0,      xr + c0,      8);
            __pipeline_memcpy_async(wb + 64 * RSTRIDE + 64 + c0, xr + 64 + c0, 8);
        }
        __pipeline_commit();
        __pipeline_wait_prior(0);
        __syncwarp();

        float2 o0 = gat_head_smem(wb, deg, satt, 0, lane, wsm);
        float2 o1 = gat_head_smem(wb, deg, satt, 64, lane, wsm);
        float v0 = 0.5f * (o0.x + o1.x) + sbias[c0];
        float v1 = 0.5f * (o0.y + o1.y) + sbias[c0 + 1];
        v0 = v0 > 0.f ? v0 : expm1f(v0);
        v1 = v1 > 0.f ? v1 : expm1f(v1);
        // g1 lives in registers: g[2*lane]=v0, g[2*lane+1]=v1

        // fused layer-2 source transform: xlout = g1 @ w2l + b2l
        {
            float a0 = b2l[c0], a1 = b2l[c0 + 1];
            float a2 = b2l[64 + c0], a3 = b2l[64 + c0 + 1];
            #pragma unroll 8
            for (int k = 0; k < 64; k++) {
                float gk = __shfl_sync(0xffffffffu, (k & 1) ? v1 : v0, k >> 1);
                float2 wA = *(const float2*)(w2l + k * 128 + c0);
                float2 wB = *(const float2*)(w2l + k * 128 + 64 + c0);
                a0 += gk * wA.x; a1 += gk * wA.y;
                a2 += gk * wB.x; a3 += gk * wB.y;
            }
            *(float2*)(xlout + c0)      = make_float2(a0, a1);
            *(float2*)(xlout + 64 + c0) = make_float2(a2, a3);
        }
        // slot-0 delta tasks also produce the target transform xr2[i]
        if (do_xr) {
            float a0 = b2r[c0], a1 = b2r[c0 + 1];
            float a2 = b2r[64 + c0], a3 = b2r[64 + c0 + 1];
            #pragma unroll 8
            for (int k = 0; k < 64; k++) {
                float gk = __shfl_sync(0xffffffffu, (k & 1) ? v1 : v0, k >> 1);
                float2 wA = *(const float2*)(w2r + k * 128 + c0);
                float2 wB = *(const float2*)(w2r + k * 128 + 64 + c0);
                a0 += gk * wA.x; a1 += gk * wA.y;
                a2 += gk * wB.x; a3 += gk * wB.y;
            }
            float* xrout = d_xr2 + isub * 128;
            *(float2*)(xrout + c0)      = make_float2(a0, a1);
            *(float2*)(xrout + 64 + c0) = make_float2(a2, a3);
        }
        __syncwarp();
    }
}

// ---------------- KC: layer-2 softmax at i + elu + reconstruction ------------
__global__ void __launch_bounds__(64) kC_final(
    const float* __restrict__ att2, const float* __restrict__ bias2,
    const float* __restrict__ recw, const float* __restrict__ recb,
    float* __restrict__ out)
{
    __shared__ __align__(16) float buf[WROWS + 128];
    __shared__ __align__(16) float satt[128];
    __shared__ __align__(16) float hC[128];
    __shared__ __align__(16) float g2s[64];
    __shared__ int sdl[DMAX];
    __shared__ int sedge[64];
    __shared__ int sslot[64];
    __shared__ int snd;

    int i = blockIdx.x;
    int tid = threadIdx.x, lane = tid & 31, h = tid >> 5;
    int hoff = h * 64;
    int c0 = 2 * lane;

    if (tid == 0) snd = d_nd[i];
    if (tid < DMAX) sdl[tid] = d_dlist[i * DMAX + tid];
    satt[tid] = att2[tid];
    satt[64 + tid] = att2[64 + tid];
    __syncthreads();
    int nd = snd;
    int b = d_rowptr[i], deg = d_rowptr[i + 1] - b;

    if (tid < deg) {
        int s = d_csrc[b + tid];
        int sl = -1;
        for (int k = 0; k < nd; k++) if (sdl[k] == s) { sl = k; break; }
        sedge[tid] = s; sslot[tid] = sl;
    }
    __syncthreads();

    for (int j = h; j < deg; j += 2) {
        int s = sedge[j], sl = sslot[j];
        const float* src = (sl >= 0) ? (d_xl2d + (i * DMAX + sl) * 128)
                                     : (d_xl20 + s * 128);
        __pipeline_memcpy_async(buf + j * RSTRIDE + c0,      src + c0,      8);
        __pipeline_memcpy_async(buf + j * RSTRIDE + 64 + c0, src + 64 + c0, 8);
    }
    {
        const float* xr = d_xr2 + i * 128;
        __pipeline_memcpy_async(buf + 64 * RSTRIDE + hoff + c0, xr + hoff + c0, 8);
    }
    __pipeline_commit();
    __pipeline_wait_prior(0);
    __syncthreads();

    float2 o = gat_head_smem(buf, deg, satt, hoff, lane, buf + WROWS + h * 64);
    hC[hoff + c0] = o.x; hC[hoff + c0 + 1] = o.y;
    __syncthreads();
    {
        float v = 0.5f * (hC[tid] + hC[64 + tid]) + bias2[tid];
        g2s[tid] = v > 0.f ? v : expm1f(v);
    }
    __syncthreads();
    {
        float a = recb[tid];
        #pragma unroll 8
        for (int c = 0; c < 64; c++) a += g2s[c] * recw[c * 64 + tid];
        out[i * 64 + tid] = tanhf(a);
    }
}

// ---------------- launch ----------------
extern "C" void kernel_launch(void* const* d_in, const int* in_sizes, int n_in,
                              void* d_out, int out_size)
{
    const float* x          = (const float*)d_in[0];
    const float* E_emb      = (const float*)d_in[1];
    const int*   edge_index = (const int*)  d_in[2];
    const float* node_proj  = (const float*)d_in[3];
    const float* emb_proj   = (const float*)d_in[4];
    const float* conv_w0    = (const float*)d_in[5];
    const float* conv_w1    = (const float*)d_in[6];
    const float* conv_b     = (const float*)d_in[7];
    const float* lin2_w     = (const float*)d_in[8];
    const float* lin2_b     = (const float*)d_in[9];
    const float* masked_proj= (const float*)d_in[10];
    const float* normal_proj= (const float*)d_in[11];
    const float* g1_wl      = (const float*)d_in[12];
    const float* g1_bl      = (const float*)d_in[13];
    const float* g1_wr      = (const float*)d_in[14];
    const float* g1_br      = (const float*)d_in[15];
    const float* g1_att     = (const float*)d_in[16];
    const float* g1_bias    = (const float*)d_in[17];
    const float* g2_wl      = (const float*)d_in[18];
    const float* g2_bl      = (const float*)d_in[19];
    const float* g2_wr      = (const float*)d_in[20];
    const float* g2_br      = (const float*)d_in[21];
    const float* g2_att     = (const float*)d_in[22];
    const float* g2_bias    = (const float*)d_in[23];
    const float* rec_w      = (const float*)d_in[24];
    const float* rec_b      = (const float*)d_in[25];
    float* out = (float*)d_out;

    int E = in_sizes[2] / 2;

    int kA_smem = (KA_WARPS * WBUF + 192) * 4;
    cudaFuncSetAttribute(k1_precompute, cudaFuncAttributeMaxDynamicSharedMemorySize, 149504);
    cudaFuncSetAttribute(kA_gat1, cudaFuncAttributeMaxDynamicSharedMemorySize, kA_smem);

    k1_precompute<<<NN / 4, 256, 149504>>>(x, E_emb, node_proj, emb_proj,
                                           conv_w0, conv_w1, conv_b,
                                           lin2_w, lin2_b, masked_proj, normal_proj,
                                           g1_wl, g1_bl, g1_wr, g1_br);
    k2_csr<<<1, 1024>>>(edge_index, E);
    kA_gat1<<<148, KA_WARPS * 32, kA_smem>>>(g1_att, g1_bias,
                                             g2_wl, g2_bl, g2_wr, g2_br);
    kC_final<<<NN, 64>>>(g2_att, g2_bias, rec_w, rec_b, out);
}

// round 14
// speedup vs baseline: 1.2144x; 1.2144x over previous
#include <cuda_runtime.h>
#include <cuda_pipeline.h>
#include <math.h>
#include <float.h>

#define NN 256
#define EMAX 8704
#define DMAX 16
#define RSTRIDE 130            // padded row stride (floats) in staging buffers
#define WROWS (65 * RSTRIDE)   // 64 src rows + 1 xr row
#define WBUF (WROWS + 64)      // + 64-float edge-weight strip, per warp
#define KA_WARPS 5
#define KC_HSZ (WROWS + 128 + 128 + 64)   // buf + wsm(in buf) + hC + g2s floats per half

// ---------------- scratch ----------------
__device__ __align__(16) float d_xl0[NN * 128];
__device__ __align__(16) float d_xr0[NN * 128];
__device__ __align__(16) float d_xlM[NN * 128];
__device__ __align__(16) float d_xrM[NN * 128];
__device__ __align__(16) float d_xl20[NN * 128];
__device__ __align__(16) float d_g10[NN * 64];
__device__ __align__(16) float d_g1d[NN * DMAX * 64];
__device__ __align__(16) float d_xl2d[NN * DMAX * 128];
__device__ __align__(16) float d_xr2[NN * 128];
__device__ int   d_rowptr[NN + 1];
__device__ int   d_csrc[EMAX];
__device__ int   d_colptr[NN + 1];
__device__ int   d_cdst[EMAX];
__device__ int   d_dlist[NN * DMAX];
__device__ int   d_nd[NN];
__device__ int   d_dtasks[NN * DMAX];
__device__ int   d_ntask;

__device__ __forceinline__ float warp_sum(float v) {
    v += __shfl_xor_sync(0xffffffffu, v, 16);
    v += __shfl_xor_sync(0xffffffffu, v, 8);
    v += __shfl_xor_sync(0xffffffffu, v, 4);
    v += __shfl_xor_sync(0xffffffffu, v, 2);
    v += __shfl_xor_sync(0xffffffffu, v, 1);
    return v;
}
__device__ __forceinline__ float warp_max(float v) {
    v = fmaxf(v, __shfl_xor_sync(0xffffffffu, v, 16));
    v = fmaxf(v, __shfl_xor_sync(0xffffffffu, v, 8));
    v = fmaxf(v, __shfl_xor_sync(0xffffffffu, v, 4));
    v = fmaxf(v, __shfl_xor_sync(0xffffffffu, v, 2));
    v = fmaxf(v, __shfl_xor_sync(0xffffffffu, v, 1));
    return v;
}

// GAT softmax for one (target, head) from a staged smem buffer.
__device__ __forceinline__ float2 gat_head_smem(
    const float* __restrict__ wb, int deg,
    const float* __restrict__ satt, int hoff, int lane, float* __restrict__ wsm)
{
    int c0 = 2 * lane;
    const float* xrp = wb + 64 * RSTRIDE + hoff;
    float lg1 = -1e30f, lg2 = -1e30f;
    if (lane < deg) {
        const float* r = wb + lane * RSTRIDE + hoff;
        float acc = 0.f;
        #pragma unroll
        for (int c = 0; c < 64; c += 2) {
            float vx = r[c], vy = r[c + 1];
            float t0 = vx + xrp[c];     t0 = t0 > 0.f ? t0 : 0.2f * t0;
            float t1 = vy + xrp[c + 1]; t1 = t1 > 0.f ? t1 : 0.2f * t1;
            acc += satt[hoff + c] * t0 + satt[hoff + c + 1] * t1;
        }
        lg1 = acc;
    }
    if (32 + lane < deg) {
        const float* r = wb + (32 + lane) * RSTRIDE + hoff;
        float acc = 0.f;
        #pragma unroll
        for (int c = 0; c < 64; c += 2) {
            float vx = r[c], vy = r[c + 1];
            float t0 = vx + xrp[c];     t0 = t0 > 0.f ? t0 : 0.2f * t0;
            float t1 = vy + xrp[c + 1]; t1 = t1 > 0.f ? t1 : 0.2f * t1;
            acc += satt[hoff + c] * t0 + satt[hoff + c + 1] * t1;
        }
        lg2 = acc;
    }
    float m = warp_max(fmaxf(lg1, lg2));
    float w1 = (lane < deg)      ? __expf(lg1 - m) : 0.f;
    float w2 = (32 + lane < deg) ? __expf(lg2 - m) : 0.f;
    float denom = warp_sum(w1 + w2);

    wsm[lane] = w1;
    wsm[32 + lane] = w2;
    __syncwarp();

    float ax = 0.f, ay = 0.f;
    #pragma unroll 4
    for (int j = 0; j < deg; j++) {
        float wj = wsm[j];
        float2 v = *(const float2*)(wb + j * RSTRIDE + hoff + c0);
        ax += wj * v.x; ay += wj * v.y;
    }
    __syncwarp();
    float inv = 1.f / (denom + 1e-16f);
    return make_float2(ax * inv, ay * inv);
}

// ---------------- async staging helper (cp.async, 16B granules) --------------
__device__ __forceinline__ void stage_async(const float* __restrict__ g, float* s, int n, int tid) {
    const float4* g4 = (const float4*)g;
    float4* s4 = (float4*)s;
    for (int idx = tid; idx < (n >> 2); idx += 256)
        __pipeline_memcpy_async(s4 + idx, g4 + idx, 16);
}

// ---------------- K1: fused precompute, 4 rows/CTA, 3 staging phases ----------
__global__ void __launch_bounds__(256) k1_precompute(
    const float* __restrict__ x, const float* __restrict__ E_emb,
    const float* __restrict__ node_proj, const float* __restrict__ emb_proj,
    const float* __restrict__ conv_w0, const float* __restrict__ conv_w1,
    const float* __restrict__ conv_b,
    const float* __restrict__ lin2_w, const float* __restrict__ lin2_b,
    const float* __restrict__ masked_proj, const float* __restrict__ normal_proj,
    const float* __restrict__ g1_wl, const float* __restrict__ g1_bl,
    const float* __restrict__ g1_wr, const float* __restrict__ g1_br)
{
    extern __shared__ __align__(16) float smem[];
    float* sW   = smem;           // 32768
    float* sx   = sW + 32768;
    float* sE   = sx + 256;
    float* sxp  = sE + 256;
    float* sEp  = sxp + 512;
    float* sh0  = sEp + 512;
    float* shM  = sh0 + 512;
    float* sm0  = shM + 512;
    float* smM  = sm0 + 256;
    float* sp0  = smM + 256;
    float* spM  = sp0 + 256;
    float* sTmp = spM + 256;      // 1024

    int tid = threadIdx.x;
    int r0 = blockIdx.x * 4;

    stage_async(node_proj, sW, 8192, tid);
    stage_async(emb_proj,  sW + 8192, 8192, tid);
    __pipeline_commit();

    sx[tid] = x[r0 * 64 + tid];
    sE[tid] = E_emb[r0 * 64 + tid];

    __pipeline_wait_prior(0);
    __syncthreads();
    {
        int half = tid >> 7, c = tid & 127;
        const float* W = sW + half * 8192;
        const float* in = half ? sE : sx;
        float a0 = 0.f, a1 = 0.f, a2 = 0.f, a3 = 0.f;
        #pragma unroll 8
        for (int k = 0; k < 64; k++) {
            float w = W[k * 128 + c];
            a0 += in[k] * w; a1 += in[64 + k] * w;
            a2 += in[128 + k] * w; a3 += in[192 + k] * w;
        }
        float* o = half ? sEp : sxp;
        o[c] = a0; o[128 + c] = a1; o[256 + c] = a2; o[384 + c] = a3;
    }
    __syncthreads();

    stage_async(conv_w1, sW, 16384, tid);
    stage_async(conv_w0, sW + 16384, 16384, tid);
    __pipeline_commit();
    __pipeline_wait_prior(0);
    __syncthreads();
    {
        int half = tid >> 7, c = tid & 127;
        const float* W = sW + half * 16384;
        const float* in = half ? sEp : sxp;
        float a0 = 0.f, a1 = 0.f, a2 = 0.f, a3 = 0.f;
        #pragma unroll 8
        for (int k = 0; k < 128; k++) {
            float w = W[k * 128 + c];
            a0 += in[k] * w; a1 += in[128 + k] * w;
            a2 += in[256 + k] * w; a3 += in[384 + k] * w;
        }
        float* o = sTmp + half * 512;
        o[c] = a0; o[128 + c] = a1; o[256 + c] = a2; o[384 + c] = a3;
    }
    __syncthreads();
    stage_async(lin2_w,      sW, 8192, tid);
    stage_async(normal_proj, sW + 8192, 4096, tid);
    stage_async(masked_proj, sW + 12288, 4096, tid);
    stage_async(g1_wl,       sW + 16384, 8192, tid);
    stage_async(g1_wr,       sW + 24576, 8192, tid);
    __pipeline_commit();

    if (tid < 128) {
        float cb = conv_b[tid];
        #pragma unroll
        for (int r = 0; r < 4; r++) {
            float xw1 = sTmp[r * 128 + tid];
            float bM  = sTmp[512 + r * 128 + tid] + cb;
            sh0[r * 128 + tid] = tanhf(bM + xw1);
            shM[r * 128 + tid] = tanhf(bM);
        }
    }
    __pipeline_wait_prior(0);
    __syncthreads();

    {
        int v = tid >> 7, kh = (tid >> 6) & 1, c = tid & 63;
        const float* hs = v ? shM : sh0;
        float a0 = 0.f, a1 = 0.f, a2 = 0.f, a3 = 0.f;
        #pragma unroll 8
        for (int kk = 0; kk < 64; kk++) {
            int k = kh * 64 + kk;
            float w = sW[k * 64 + c];
            a0 += hs[k] * w; a1 += hs[128 + k] * w;
            a2 += hs[256 + k] * w; a3 += hs[384 + k] * w;
        }
        float* o = sTmp + v * 512 + kh * 64;
        o[c] = a0; o[128 + c] = a1; o[256 + c] = a2; o[384 + c] = a3;
    }
    __syncthreads();
    {
        int v = tid >> 7, rp = (tid >> 6) & 1, c = tid & 63;
        float lb = lin2_b[c];
        float* d = v ? smM : sm0;
        #pragma unroll
        for (int rr = 0; rr < 2; rr++) {
            int r = rp * 2 + rr;
            d[r * 64 + c] = sTmp[v * 512 + r * 128 + c] + sTmp[v * 512 + r * 128 + 64 + c] + lb;
        }
    }
    __syncthreads();

    {
        int v = tid >> 7, rp = (tid >> 6) & 1, c = tid & 63;
        const float* s = v ? smM : sm0;
        const float* W = sW + 8192 + v * 4096;
        float* d = v ? spM : sp0;
        float a0 = 0.f, a1 = 0.f;
        int r = rp * 2;
        #pragma unroll 8
        for (int k = 0; k < 64; k++) {
            float w = W[k * 64 + c];
            a0 += s[r * 64 + k] * w; a1 += s[(r + 1) * 64 + k] * w;
        }
        d[r * 64 + c] = a0; d[(r + 1) * 64 + c] = a1;
    }
    __syncthreads();

    {
        int half = tid >> 7, c = tid & 127;
        const float* W = sW + 16384 + half * 8192;
        float b0[4] = {0.f, 0.f, 0.f, 0.f};
        float bm[4] = {0.f, 0.f, 0.f, 0.f};
        #pragma unroll 8
        for (int k = 0; k < 64; k++) {
            float w = W[k * 128 + c];
            #pragma unroll
            for (int r = 0; r < 4; r++) {
                b0[r] += sp0[r * 64 + k] * w;
                bm[r] += spM[r * 64 + k] * w;
            }
        }
        float bb = half ? g1_br[c] : g1_bl[c];
        float* o0 = half ? d_xr0 : d_xl0;
        float* oM = half ? d_xrM : d_xlM;
        #pragma unroll
        for (int r = 0; r < 4; r++) {
            o0[(r0 + r) * 128 + c] = b0[r] + bb;
            oM[(r0 + r) * 128 + c] = bm[r] + bb;
        }
    }
}

// ---------------- K2: CSR (by dst) + CSC (by src) ----------------
__global__ void __launch_bounds__(1024) k2_csr(const int* __restrict__ ei, int E)
{
    __shared__ int c1[NN], c2[NN], cur1[NN], cur2[NN];
    __shared__ int ws[16];
    int tid = threadIdx.x;
    if (tid == 0) d_ntask = 0;
    if (tid < NN) { c1[tid] = 0; c2[tid] = 0; }
    __syncthreads();
    const int* src = ei;
    const int* dst = ei + E;
    for (int e = tid; e < E; e += 1024) {
        atomicAdd(&c1[dst[e]], 1);
        atomicAdd(&c2[src[e]], 1);
    }
    __syncthreads();
    if (tid < NN) {
        int lane = tid & 31, wid = tid >> 5;
        int v1 = c1[tid], v2 = c2[tid];
        int x1 = v1, x2 = v2;
        #pragma unroll
        for (int d = 1; d < 32; d <<= 1) {
            int y1 = __shfl_up_sync(0xffffffffu, x1, d);
            int y2 = __shfl_up_sync(0xffffffffu, x2, d);
            if (lane >= d) { x1 += y1; x2 += y2; }
        }
        if (lane == 31) { ws[wid] = x1; ws[8 + wid] = x2; }
    }
    __syncthreads();
    if (tid == 0) {
        int a = 0, b = 0;
        for (int w = 0; w < 8; w++) {
            int t1 = ws[w], t2 = ws[8 + w];
            ws[w] = a; ws[8 + w] = b;
            a += t1; b += t2;
        }
    }
    __syncthreads();
    if (tid < NN) {
        int lane = tid & 31, wid = tid >> 5;
        int v1 = c1[tid], v2 = c2[tid];
        int x1 = v1, x2 = v2;
        #pragma unroll
        for (int d = 1; d < 32; d <<= 1) {
            int y1 = __shfl_up_sync(0xffffffffu, x1, d);
            int y2 = __shfl_up_sync(0xffffffffu, x2, d);
            if (lane >= d) { x1 += y1; x2 += y2; }
        }
        int ex1 = ws[wid] + x1 - v1;
        int ex2 = ws[8 + wid] + x2 - v2;
        d_rowptr[tid] = ex1; d_colptr[tid] = ex2;
        cur1[tid] = ex1; cur2[tid] = ex2;
        if (tid == NN - 1) { d_rowptr[NN] = ex1 + v1; d_colptr[NN] = ex2 + v2; }
    }
    __syncthreads();
    for (int e = tid; e < E; e += 1024) {
        int p1 = atomicAdd(&cur1[dst[e]], 1); d_csrc[p1] = src[e];
        int p2 = atomicAdd(&cur2[src[e]], 1); d_cdst[p2] = dst[e];
    }
}

// ---------------- KD: per-instance delta lists + compacted task array --------
__global__ void __launch_bounds__(128) kD_dlist()
{
    __shared__ int innb[NN];
    __shared__ int scd[128];
    int i = blockIdx.x, tid = threadIdx.x;
    for (int k = tid; k < NN; k += 128) innb[k] = 0;
    __syncthreads();
    int b = d_rowptr[i], e = d_rowptr[i + 1];
    for (int p = b + tid; p < e; p += 128) innb[d_csrc[p]] = 1;
    int cb = d_colptr[i], ce = d_colptr[i + 1];
    int odeg = min(ce - cb, 128);
    if (tid < odeg) scd[tid] = d_cdst[cb + tid];
    __syncthreads();
    if (tid == 0) {
        int dl[DMAX];
        int nd = 1;
        dl[0] = i;
        innb[i] |= 2;
        for (int p = 0; p < odeg && nd < DMAX; p++) {
            int t = scd[p];
            int f = innb[t];
            if ((f & 1) && !(f & 2)) { innb[t] = f | 2; dl[nd++] = t; }
        }
        d_nd[i] = nd;
        int base = atomicAdd(&d_ntask, nd);
        for (int k = 0; k < nd; k++) {
            d_dlist[i * DMAX + k] = dl[k];
            d_dtasks[base + k] = i * DMAX + k;
        }
    }
}

// ---------------- KA: all layer-1 GAT tasks, cp.async staged rows ------------
__global__ void __launch_bounds__(KA_WARPS * 32) kA_gat1(
    const float* __restrict__ att1, const float* __restrict__ bias1)
{
    extern __shared__ __align__(16) float sbuf[];
    float* satt  = sbuf + KA_WARPS * WBUF;   // 128
    float* sbias = satt + 128;               // 64

    int tid = threadIdx.x, lane = tid & 31, wid = tid >> 5;
    if (tid < 128) satt[tid] = att1[tid];
    if (tid < 64)  sbias[tid] = bias1[tid];
    __syncthreads();

    float* wb  = sbuf + wid * WBUF;
    float* wsm = wb + WROWS;
    int c0 = 2 * lane;
    int step = gridDim.x * KA_WARPS;
    int total = NN + d_ntask;

    for (int task = blockIdx.x * KA_WARPS + wid; task < total; task += step) {
        int t, isub;
        float* outp;
        if (task < NN) {
            t = task; isub = -1; outp = d_g10 + t * 64;
        } else {
            int v = d_dtasks[task - NN];
            isub = v >> 4;           // DMAX = 16
            t = d_dlist[v];
            outp = d_g1d + v * 64;
        }
        int b = d_rowptr[t], deg = d_rowptr[t + 1] - b;

        int s1 = (lane < deg)      ? d_csrc[b + lane]      : 0;
        int s2 = (32 + lane < deg) ? d_csrc[b + 32 + lane] : 0;
        for (int j = 0; j < deg; j++) {
            int s = __shfl_sync(0xffffffffu, (j < 32) ? s1 : s2, j & 31);
            const float* src = (s == isub) ? (d_xlM + s * 128) : (d_xl0 + s * 128);
            __pipeline_memcpy_async(wb + j * RSTRIDE + c0,      src + c0,      8);
            __pipeline_memcpy_async(wb + j * RSTRIDE + 64 + c0, src + 64 + c0, 8);
        }
        {
            const float* xr = (t == isub) ? (d_xrM + t * 128) : (d_xr0 + t * 128);
            __pipeline_memcpy_async(wb + 64 * RSTRIDE + c0,      xr + c0,      8);
            __pipeline_memcpy_async(wb + 64 * RSTRIDE + 64 + c0, xr + 64 + c0, 8);
        }
        __pipeline_commit();
        __pipeline_wait_prior(0);
        __syncwarp();

        float2 o0 = gat_head_smem(wb, deg, satt, 0, lane, wsm);
        float2 o1 = gat_head_smem(wb, deg, satt, 64, lane, wsm);
        float v0 = 0.5f * (o0.x + o1.x) + sbias[c0];
        float v1 = 0.5f * (o0.y + o1.y) + sbias[c0 + 1];
        v0 = v0 > 0.f ? v0 : expm1f(v0);
        v1 = v1 > 0.f ? v1 : expm1f(v1);
        *(float2*)(outp + c0) = make_float2(v0, v1);
        __syncwarp();
    }
}

// ---------------- KB: all layer-2 transform matvecs, weights in smem ---------
__global__ void __launch_bounds__(256) kB_xform(
    const float* __restrict__ w2l, const float* __restrict__ b2l,
    const float* __restrict__ w2r, const float* __restrict__ b2r)
{
    extern __shared__ __align__(16) float sw[];  // w2l 8192 + w2r 8192
    int tid = threadIdx.x, lane = tid & 31, wid = tid >> 5;
    int total = 2 * NN + d_ntask;
    if (blockIdx.x * 8 >= total) return;

    stage_async(w2l, sw, 8192, tid);
    stage_async(w2r, sw + 8192, 8192, tid);
    __pipeline_commit();
    __pipeline_wait_prior(0);
    __syncthreads();

    int c0 = 2 * lane;
    int step = gridDim.x * 8;
    for (int task = blockIdx.x * 8 + wid; task < total; task += step) {
        const float* g;
        const float* W;
        const float* bb;
        float* outp;
        if (task < NN) {
            g = d_g10 + task * 64; W = sw; bb = b2l; outp = d_xl20 + task * 128;
        } else if (task < 2 * NN) {
            int i = task - NN;
            g = d_g1d + (i * DMAX) * 64; W = sw + 8192; bb = b2r; outp = d_xr2 + i * 128;
        } else {
            int v = d_dtasks[task - 2 * NN];
            g = d_g1d + v * 64; W = sw; bb = b2l; outp = d_xl2d + v * 128;
        }
        float a0 = bb[c0], a1 = bb[c0 + 1];
        float a2 = bb[64 + c0], a3 = bb[64 + c0 + 1];
        #pragma unroll 8
        for (int k = 0; k < 64; k++) {
            float gk = g[k];
            float2 wA = *(const float2*)(W + k * 128 + c0);
            float2 wB = *(const float2*)(W + k * 128 + 64 + c0);
            a0 += gk * wA.x; a1 += gk * wA.y;
            a2 += gk * wB.x; a3 += gk * wB.y;
        }
        *(float2*)(outp + c0)      = make_float2(a0, a1);
        *(float2*)(outp + 64 + c0) = make_float2(a2, a3);
    }
}

// ---------------- KC: layer-2 softmax + recon, 2 instances per CTA -----------
__global__ void __launch_bounds__(128) kC_final(
    const float* __restrict__ att2, const float* __restrict__ bias2,
    const float* __restrict__ recw, const float* __restrict__ recb,
    float* __restrict__ out)
{
    extern __shared__ __align__(16) float dyn[];
    float* satt = dyn;                                   // 128
    int tid = threadIdx.x;
    int half = tid >> 6, ltid = tid & 63;
    int lane = ltid & 31, h = ltid >> 5;

    float* buf = dyn + 128 + half * KC_HSZ;              // WROWS + 128 (wsm)
    float* hC  = buf + (WROWS + 128);                    // 128
    float* g2s = hC + 128;                               // 64
    int* ints  = (int*)(dyn + 128 + 2 * KC_HSZ) + half * 160;
    int* sdl   = ints;          // DMAX
    int* sedge = ints + 16;     // 64
    int* sslot = ints + 80;     // 64
    int* snd   = ints + 144;    // 1

    int i = blockIdx.x * 2 + half;
    int hoff = h * 64;
    int c0 = 2 * lane;

    satt[tid] = att2[tid];
    if (ltid == 0) *snd = d_nd[i];
    if (ltid < DMAX) sdl[ltid] = d_dlist[i * DMAX + ltid];
    __syncthreads();
    int nd = *snd;
    int b = d_rowptr[i], deg = d_rowptr[i + 1] - b;

    if (ltid < deg) {
        int s = d_csrc[b + ltid];
        int sl = -1;
        for (int k = 0; k < nd; k++) if (sdl[k] == s) { sl = k; break; }
        sedge[ltid] = s; sslot[ltid] = sl;
    }
    asm volatile("bar.sync %0, 64;" :: "r"(half + 1) : "memory");

    for (int j = h; j < deg; j += 2) {
        int s = sedge[j], sl = sslot[j];
        const float* src = (sl >= 0) ? (d_xl2d + (i * DMAX + sl) * 128)
                                     : (d_xl20 + s * 128);
        __pipeline_memcpy_async(buf + j * RSTRIDE + c0,      src + c0,      8);
        __pipeline_memcpy_async(buf + j * RSTRIDE + 64 + c0, src + 64 + c0, 8);
    }
    {
        const float* xr = d_xr2 + i * 128;
        __pipeline_memcpy_async(buf + 64 * RSTRIDE + hoff + c0, xr + hoff + c0, 8);
    }
    __pipeline_commit();
    __pipeline_wait_prior(0);
    asm volatile("bar.sync %0, 64;" :: "r"(half + 1) : "memory");

    float2 o = gat_head_smem(buf, deg, satt, hoff, lane, buf + WROWS + h * 64);
    hC[hoff + c0] = o.x; hC[hoff + c0 + 1] = o.y;
    asm volatile("bar.sync %0, 64;" :: "r"(half + 1) : "memory");
    {
        float v = 0.5f * (hC[ltid] + hC[64 + ltid]) + bias2[ltid];
        g2s[ltid] = v > 0.f ? v : expm1f(v);
    }
    asm volatile("bar.sync %0, 64;" :: "r"(half + 1) : "memory");
    {
        float a = recb[ltid];
        #pragma unroll 8
        for (int c = 0; c < 64; c++) a += g2s[c] * recw[c * 64 + ltid];
        out[i * 64 + ltid] = tanhf(a);
    }
}

// ---------------- launch ----------------
extern "C" void kernel_launch(void* const* d_in, const int* in_sizes, int n_in,
                              void* d_out, int out_size)
{
    const float* x          = (const float*)d_in[0];
    const float* E_emb      = (const float*)d_in[1];
    const int*   edge_index = (const int*)  d_in[2];
    const float* node_proj  = (const float*)d_in[3];
    const float* emb_proj   = (const float*)d_in[4];
    const float* conv_w0    = (const float*)d_in[5];
    const float* conv_w1    = (const float*)d_in[6];
    const float* conv_b     = (const float*)d_in[7];
    const float* lin2_w     = (const float*)d_in[8];
    const float* lin2_b     = (const float*)d_in[9];
    const float* masked_proj= (const float*)d_in[10];
    const float* normal_proj= (const float*)d_in[11];
    const float* g1_wl      = (const float*)d_in[12];
    const float* g1_bl      = (const float*)d_in[13];
    const float* g1_wr      = (const float*)d_in[14];
    const float* g1_br      = (const float*)d_in[15];
    const float* g1_att     = (const float*)d_in[16];
    const float* g1_bias    = (const float*)d_in[17];
    const float* g2_wl      = (const float*)d_in[18];
    const float* g2_bl      = (const float*)d_in[19];
    const float* g2_wr      = (const float*)d_in[20];
    const float* g2_br      = (const float*)d_in[21];
    const float* g2_att     = (const float*)d_in[22];
    const float* g2_bias    = (const float*)d_in[23];
    const float* rec_w      = (const float*)d_in[24];
    const float* rec_b      = (const float*)d_in[25];
    float* out = (float*)d_out;

    int E = in_sizes[2] / 2;

    int kA_smem = (KA_WARPS * WBUF + 192) * 4;
    int kC_smem = (128 + 2 * KC_HSZ + 320) * 4;
    cudaFuncSetAttribute(k1_precompute, cudaFuncAttributeMaxDynamicSharedMemorySize, 149504);
    cudaFuncSetAttribute(kA_gat1, cudaFuncAttributeMaxDynamicSharedMemorySize, kA_smem);
    cudaFuncSetAttribute(kB_xform, cudaFuncAttributeMaxDynamicSharedMemorySize, 65536);
    cudaFuncSetAttribute(kC_final, cudaFuncAttributeMaxDynamicSharedMemorySize, kC_smem);

    k1_precompute<<<NN / 4, 256, 149504>>>(x, E_emb, node_proj, emb_proj,
                                           conv_w0, conv_w1, conv_b,
                                           lin2_w, lin2_b, masked_proj, normal_proj,
                                           g1_wl, g1_bl, g1_wr, g1_br);
    k2_csr<<<1, 1024>>>(edge_index, E);
    kD_dlist<<<NN, 128>>>();
    kA_gat1<<<296, KA_WARPS * 32, kA_smem>>>(g1_att, g1_bias);
    kB_xform<<<99, 256, 65536>>>(g2_wl, g2_bl, g2_wr, g2_br);
    kC_final<<<NN / 2, 128, kC_smem>>>(g2_att, g2_bias, rec_w, rec_b, out);
}

// round 15
// speedup vs baseline: 1.3764x; 1.1334x over previous
#include <cuda_runtime.h>
#include <cuda_pipeline.h>
#include <math.h>
#include <float.h>

#define NN 256
#define EMAX 8704
#define DMAX 16
#define RSTRIDE 130            // padded row stride (floats) in staging buffers
#define WROWS (65 * RSTRIDE)   // 64 src rows + 1 xr row
#define PBUF (WROWS + 128)     // pair buffer: rows + 128-float weight/combine strip
#define KA_PAIRS 3             // pairs per CTA (6 warps)

// ---------------- scratch ----------------
__device__ __align__(16) float d_xl0[NN * 128];
__device__ __align__(16) float d_xr0[NN * 128];
__device__ __align__(16) float d_xlM[NN * 128];
__device__ __align__(16) float d_xrM[NN * 128];
__device__ __align__(16) float d_xl20[NN * 128];
__device__ __align__(16) float d_g10[NN * 64];
__device__ __align__(16) float d_g1d[NN * DMAX * 64];
__device__ __align__(16) float d_xl2d[NN * DMAX * 128];
__device__ __align__(16) float d_xr2[NN * 128];
__device__ int   d_rowptr[NN + 1];
__device__ int   d_csrc[EMAX];
__device__ int   d_colptr[NN + 1];
__device__ int   d_cdst[EMAX];
__device__ int   d_dlist[NN * DMAX];
__device__ int   d_nd[NN];
__device__ int   d_dtasks[NN * DMAX];
__device__ int   d_ntask;

__device__ __forceinline__ float warp_sum(float v) {
    v += __shfl_xor_sync(0xffffffffu, v, 16);
    v += __shfl_xor_sync(0xffffffffu, v, 8);
    v += __shfl_xor_sync(0xffffffffu, v, 4);
    v += __shfl_xor_sync(0xffffffffu, v, 2);
    v += __shfl_xor_sync(0xffffffffu, v, 1);
    return v;
}
__device__ __forceinline__ float warp_max(float v) {
    v = fmaxf(v, __shfl_xor_sync(0xffffffffu, v, 16));
    v = fmaxf(v, __shfl_xor_sync(0xffffffffu, v, 8));
    v = fmaxf(v, __shfl_xor_sync(0xffffffffu, v, 4));
    v = fmaxf(v, __shfl_xor_sync(0xffffffffu, v, 2));
    v = fmaxf(v, __shfl_xor_sync(0xffffffffu, v, 1));
    return v;
}

// GAT softmax for one (target, head) from a staged smem buffer.
__device__ __forceinline__ float2 gat_head_smem(
    const float* __restrict__ wb, int deg,
    const float* __restrict__ satt, int hoff, int lane, float* __restrict__ wsm)
{
    int c0 = 2 * lane;
    const float* xrp = wb + 64 * RSTRIDE + hoff;
    float lg1 = -1e30f, lg2 = -1e30f;
    if (lane < deg) {
        const float* r = wb + lane * RSTRIDE + hoff;
        float acc = 0.f;
        #pragma unroll
        for (int c = 0; c < 64; c += 2) {
            float vx = r[c], vy = r[c + 1];
            float t0 = vx + xrp[c];     t0 = t0 > 0.f ? t0 : 0.2f * t0;
            float t1 = vy + xrp[c + 1]; t1 = t1 > 0.f ? t1 : 0.2f * t1;
            acc += satt[hoff + c] * t0 + satt[hoff + c + 1] * t1;
        }
        lg1 = acc;
    }
    if (32 + lane < deg) {
        const float* r = wb + (32 + lane) * RSTRIDE + hoff;
        float acc = 0.f;
        #pragma unroll
        for (int c = 0; c < 64; c += 2) {
            float vx = r[c], vy = r[c + 1];
            float t0 = vx + xrp[c];     t0 = t0 > 0.f ? t0 : 0.2f * t0;
            float t1 = vy + xrp[c + 1]; t1 = t1 > 0.f ? t1 : 0.2f * t1;
            acc += satt[hoff + c] * t0 + satt[hoff + c + 1] * t1;
        }
        lg2 = acc;
    }
    float m = warp_max(fmaxf(lg1, lg2));
    float w1 = (lane < deg)      ? __expf(lg1 - m) : 0.f;
    float w2 = (32 + lane < deg) ? __expf(lg2 - m) : 0.f;
    float denom = warp_sum(w1 + w2);

    wsm[lane] = w1;
    wsm[32 + lane] = w2;
    __syncwarp();

    float ax = 0.f, ay = 0.f;
    #pragma unroll 4
    for (int j = 0; j < deg; j++) {
        float wj = wsm[j];
        float2 v = *(const float2*)(wb + j * RSTRIDE + hoff + c0);
        ax += wj * v.x; ay += wj * v.y;
    }
    __syncwarp();
    float inv = 1.f / (denom + 1e-16f);
    return make_float2(ax * inv, ay * inv);
}

// ---------------- async staging helper (cp.async, 16B granules) --------------
__device__ __forceinline__ void stage_async(const float* __restrict__ g, float* s, int n, int tid) {
    const float4* g4 = (const float4*)g;
    float4* s4 = (float4*)s;
    for (int idx = tid; idx < (n >> 2); idx += 256)
        __pipeline_memcpy_async(s4 + idx, g4 + idx, 16);
}

// ---------------- K1: fused precompute, 4 rows/CTA, 3 staging phases ----------
__global__ void __launch_bounds__(256) k1_precompute(
    const float* __restrict__ x, const float* __restrict__ E_emb,
    const float* __restrict__ node_proj, const float* __restrict__ emb_proj,
    const float* __restrict__ conv_w0, const float* __restrict__ conv_w1,
    const float* __restrict__ conv_b,
    const float* __restrict__ lin2_w, const float* __restrict__ lin2_b,
    const float* __restrict__ masked_proj, const float* __restrict__ normal_proj,
    const float* __restrict__ g1_wl, const float* __restrict__ g1_bl,
    const float* __restrict__ g1_wr, const float* __restrict__ g1_br)
{
    extern __shared__ __align__(16) float smem[];
    float* sW   = smem;           // 32768
    float* sx   = sW + 32768;
    float* sE   = sx + 256;
    float* sxp  = sE + 256;
    float* sEp  = sxp + 512;
    float* sh0  = sEp + 512;
    float* shM  = sh0 + 512;
    float* sm0  = shM + 512;
    float* smM  = sm0 + 256;
    float* sp0  = smM + 256;
    float* spM  = sp0 + 256;
    float* sTmp = spM + 256;      // 1024

    int tid = threadIdx.x;
    int r0 = blockIdx.x * 4;

    stage_async(node_proj, sW, 8192, tid);
    stage_async(emb_proj,  sW + 8192, 8192, tid);
    __pipeline_commit();

    sx[tid] = x[r0 * 64 + tid];
    sE[tid] = E_emb[r0 * 64 + tid];

    __pipeline_wait_prior(0);
    __syncthreads();
    {
        int half = tid >> 7, c = tid & 127;
        const float* W = sW + half * 8192;
        const float* in = half ? sE : sx;
        float a0 = 0.f, a1 = 0.f, a2 = 0.f, a3 = 0.f;
        #pragma unroll 8
        for (int k = 0; k < 64; k++) {
            float w = W[k * 128 + c];
            a0 += in[k] * w; a1 += in[64 + k] * w;
            a2 += in[128 + k] * w; a3 += in[192 + k] * w;
        }
        float* o = half ? sEp : sxp;
        o[c] = a0; o[128 + c] = a1; o[256 + c] = a2; o[384 + c] = a3;
    }
    __syncthreads();

    stage_async(conv_w1, sW, 16384, tid);
    stage_async(conv_w0, sW + 16384, 16384, tid);
    __pipeline_commit();
    __pipeline_wait_prior(0);
    __syncthreads();
    {
        int half = tid >> 7, c = tid & 127;
        const float* W = sW + half * 16384;
        const float* in = half ? sEp : sxp;
        float a0 = 0.f, a1 = 0.f, a2 = 0.f, a3 = 0.f;
        #pragma unroll 8
        for (int k = 0; k < 128; k++) {
            float w = W[k * 128 + c];
            a0 += in[k] * w; a1 += in[128 + k] * w;
            a2 += in[256 + k] * w; a3 += in[384 + k] * w;
        }
        float* o = sTmp + half * 512;
        o[c] = a0; o[128 + c] = a1; o[256 + c] = a2; o[384 + c] = a3;
    }
    __syncthreads();
    stage_async(lin2_w,      sW, 8192, tid);
    stage_async(normal_proj, sW + 8192, 4096, tid);
    stage_async(masked_proj, sW + 12288, 4096, tid);
    stage_async(g1_wl,       sW + 16384, 8192, tid);
    stage_async(g1_wr,       sW + 24576, 8192, tid);
    __pipeline_commit();

    if (tid < 128) {
        float cb = conv_b[tid];
        #pragma unroll
        for (int r = 0; r < 4; r++) {
            float xw1 = sTmp[r * 128 + tid];
            float bM  = sTmp[512 + r * 128 + tid] + cb;
            sh0[r * 128 + tid] = tanhf(bM + xw1);
            shM[r * 128 + tid] = tanhf(bM);
        }
    }
    __pipeline_wait_prior(0);
    __syncthreads();

    {
        int v = tid >> 7, kh = (tid >> 6) & 1, c = tid & 63;
        const float* hs = v ? shM : sh0;
        float a0 = 0.f, a1 = 0.f, a2 = 0.f, a3 = 0.f;
        #pragma unroll 8
        for (int kk = 0; kk < 64; kk++) {
            int k = kh * 64 + kk;
            float w = sW[k * 64 + c];
            a0 += hs[k] * w; a1 += hs[128 + k] * w;
            a2 += hs[256 + k] * w; a3 += hs[384 + k] * w;
        }
        float* o = sTmp + v * 512 + kh * 64;
        o[c] = a0; o[128 + c] = a1; o[256 + c] = a2; o[384 + c] = a3;
    }
    __syncthreads();
    {
        int v = tid >> 7, rp = (tid >> 6) & 1, c = tid & 63;
        float lb = lin2_b[c];
        float* d = v ? smM : sm0;
        #pragma unroll
        for (int rr = 0; rr < 2; rr++) {
            int r = rp * 2 + rr;
            d[r * 64 + c] = sTmp[v * 512 + r * 128 + c] + sTmp[v * 512 + r * 128 + 64 + c] + lb;
        }
    }
    __syncthreads();

    {
        int v = tid >> 7, rp = (tid >> 6) & 1, c = tid & 63;
        const float* s = v ? smM : sm0;
        const float* W = sW + 8192 + v * 4096;
        float* d = v ? spM : sp0;
        float a0 = 0.f, a1 = 0.f;
        int r = rp * 2;
        #pragma unroll 8
        for (int k = 0; k < 64; k++) {
            float w = W[k * 64 + c];
            a0 += s[r * 64 + k] * w; a1 += s[(r + 1) * 64 + k] * w;
        }
        d[r * 64 + c] = a0; d[(r + 1) * 64 + c] = a1;
    }
    __syncthreads();

    {
        int half = tid >> 7, c = tid & 127;
        const float* W = sW + 16384 + half * 8192;
        float b0[4] = {0.f, 0.f, 0.f, 0.f};
        float bm[4] = {0.f, 0.f, 0.f, 0.f};
        #pragma unroll 8
        for (int k = 0; k < 64; k++) {
            float w = W[k * 128 + c];
            #pragma unroll
            for (int r = 0; r < 4; r++) {
                b0[r] += sp0[r * 64 + k] * w;
                bm[r] += spM[r * 64 + k] * w;
            }
        }
        float bb = half ? g1_br[c] : g1_bl[c];
        float* o0 = half ? d_xr0 : d_xl0;
        float* oM = half ? d_xrM : d_xlM;
        #pragma unroll
        for (int r = 0; r < 4; r++) {
            o0[(r0 + r) * 128 + c] = b0[r] + bb;
            oM[(r0 + r) * 128 + c] = bm[r] + bb;
        }
    }
}

// ---------------- K2: CSR (by dst) + CSC (by src) ----------------
__global__ void __launch_bounds__(1024) k2_csr(const int* __restrict__ ei, int E)
{
    __shared__ int c1[NN], c2[NN], cur1[NN], cur2[NN];
    __shared__ int ws[16];
    int tid = threadIdx.x;
    if (tid == 0) d_ntask = 0;
    if (tid < NN) { c1[tid] = 0; c2[tid] = 0; }
    __syncthreads();
    const int* src = ei;
    const int* dst = ei + E;
    for (int e = tid; e < E; e += 1024) {
        atomicAdd(&c1[dst[e]], 1);
        atomicAdd(&c2[src[e]], 1);
    }
    __syncthreads();
    if (tid < NN) {
        int lane = tid & 31, wid = tid >> 5;
        int v1 = c1[tid], v2 = c2[tid];
        int x1 = v1, x2 = v2;
        #pragma unroll
        for (int d = 1; d < 32; d <<= 1) {
            int y1 = __shfl_up_sync(0xffffffffu, x1, d);
            int y2 = __shfl_up_sync(0xffffffffu, x2, d);
            if (lane >= d) { x1 += y1; x2 += y2; }
        }
        if (lane == 31) { ws[wid] = x1; ws[8 + wid] = x2; }
    }
    __syncthreads();
    if (tid == 0) {
        int a = 0, b = 0;
        for (int w = 0; w < 8; w++) {
            int t1 = ws[w], t2 = ws[8 + w];
            ws[w] = a; ws[8 + w] = b;
            a += t1; b += t2;
        }
    }
    __syncthreads();
    if (tid < NN) {
        int lane = tid & 31, wid = tid >> 5;
        int v1 = c1[tid], v2 = c2[tid];
        int x1 = v1, x2 = v2;
        #pragma unroll
        for (int d = 1; d < 32; d <<= 1) {
            int y1 = __shfl_up_sync(0xffffffffu, x1, d);
            int y2 = __shfl_up_sync(0xffffffffu, x2, d);
            if (lane >= d) { x1 += y1; x2 += y2; }
        }
        int ex1 = ws[wid] + x1 - v1;
        int ex2 = ws[8 + wid] + x2 - v2;
        d_rowptr[tid] = ex1; d_colptr[tid] = ex2;
        cur1[tid] = ex1; cur2[tid] = ex2;
        if (tid == NN - 1) { d_rowptr[NN] = ex1 + v1; d_colptr[NN] = ex2 + v2; }
    }
    __syncthreads();
    for (int e = tid; e < E; e += 1024) {
        int p1 = atomicAdd(&cur1[dst[e]], 1); d_csrc[p1] = src[e];
        int p2 = atomicAdd(&cur2[src[e]], 1); d_cdst[p2] = dst[e];
    }
}

// ---------------- KD: per-instance delta lists + compacted task array --------
__global__ void __launch_bounds__(128) kD_dlist()
{
    __shared__ int innb[NN];
    __shared__ int scd[128];
    int i = blockIdx.x, tid = threadIdx.x;
    for (int k = tid; k < NN; k += 128) innb[k] = 0;
    __syncthreads();
    int b = d_rowptr[i], e = d_rowptr[i + 1];
    for (int p = b + tid; p < e; p += 128) innb[d_csrc[p]] = 1;
    int cb = d_colptr[i], ce = d_colptr[i + 1];
    int odeg = min(ce - cb, 128);
    if (tid < odeg) scd[tid] = d_cdst[cb + tid];
    __syncthreads();
    if (tid == 0) {
        int dl[DMAX];
        int nd = 1;
        dl[0] = i;
        innb[i] |= 2;
        for (int p = 0; p < odeg && nd < DMAX; p++) {
            int t = scd[p];
            int f = innb[t];
            if ((f & 1) && !(f & 2)) { innb[t] = f | 2; dl[nd++] = t; }
        }
        d_nd[i] = nd;
        int base = atomicAdd(&d_ntask, nd);
        for (int k = 0; k < nd; k++) {
            d_dlist[i * DMAX + k] = dl[k];
            d_dtasks[base + k] = i * DMAX + k;
        }
    }
}

// ---------------- KA: layer-1 GAT, warp-pair per task, shared staging --------
__global__ void __launch_bounds__(KA_PAIRS * 64) kA_gat1(
    const float* __restrict__ att1, const float* __restrict__ bias1)
{
    extern __shared__ __align__(16) float sbuf[];
    float* satt  = sbuf + KA_PAIRS * PBUF;   // 128
    float* sbias = satt + 128;               // 64

    int tid = threadIdx.x, lane = tid & 31, wid = tid >> 5;
    int pair = wid >> 1, h = wid & 1;
    if (tid < 128) satt[tid] = att1[tid];
    if (tid < 64)  sbias[tid] = bias1[tid];
    __syncthreads();

    float* wb   = sbuf + pair * PBUF;       // 65 rows of 130
    float* strip = wb + WROWS;              // 128-float: per-warp wsm, then combine
    float* wsm  = strip + h * 64;
    int hoff = h * 64;
    int c0 = 2 * lane;
    int step = gridDim.x * KA_PAIRS;
    int total = NN + d_ntask;

    for (int task = blockIdx.x * KA_PAIRS + pair; task < total; task += step) {
        int t, isub;
        float* outp;
        if (task < NN) {
            t = task; isub = -1; outp = d_g10 + t * 64;
        } else {
            int v = d_dtasks[task - NN];
            isub = v >> 4;           // DMAX = 16
            t = d_dlist[v];
            outp = d_g1d + v * 64;
        }
        int b = d_rowptr[t], deg = d_rowptr[t + 1] - b;

        // warp h stages the hoff..hoff+64 slice of each source row + xr row
        int s1 = (lane < deg)      ? d_csrc[b + lane]      : 0;
        int s2 = (32 + lane < deg) ? d_csrc[b + 32 + lane] : 0;
        for (int j = 0; j < deg; j++) {
            int s = __shfl_sync(0xffffffffu, (j < 32) ? s1 : s2, j & 31);
            const float* src = (s == isub) ? (d_xlM + s * 128) : (d_xl0 + s * 128);
            __pipeline_memcpy_async(wb + j * RSTRIDE + hoff + c0, src + hoff + c0, 8);
        }
        {
            const float* xr = (t == isub) ? (d_xrM + t * 128) : (d_xr0 + t * 128);
            __pipeline_memcpy_async(wb + 64 * RSTRIDE + hoff + c0, xr + hoff + c0, 8);
        }
        __pipeline_commit();
        __pipeline_wait_prior(0);
        asm volatile("bar.sync %0, 64;" :: "r"(pair + 1) : "memory");

        float2 o = gat_head_smem(wb, deg, satt, hoff, lane, wsm);

        // combine heads via the (now dead) weight strip
        strip[hoff + c0]     = o.x;
        strip[hoff + c0 + 1] = o.y;
        asm volatile("bar.sync %0, 64;" :: "r"(pair + 1) : "memory");
        if (h == 0) {
            float v0 = 0.5f * (strip[c0]     + strip[64 + c0])     + sbias[c0];
            float v1 = 0.5f * (strip[c0 + 1] + strip[64 + c0 + 1]) + sbias[c0 + 1];
            v0 = v0 > 0.f ? v0 : expm1f(v0);
            v1 = v1 > 0.f ? v1 : expm1f(v1);
            *(float2*)(outp + c0) = make_float2(v0, v1);
        }
        asm volatile("bar.sync %0, 64;" :: "r"(pair + 1) : "memory");
    }
}

// ---------------- KB: all layer-2 transform matvecs, weights in smem ---------
__global__ void __launch_bounds__(256) kB_xform(
    const float* __restrict__ w2l, const float* __restrict__ b2l,
    const float* __restrict__ w2r, const float* __restrict__ b2r)
{
    extern __shared__ __align__(16) float sw[];  // w2l 8192 + w2r 8192
    int tid = threadIdx.x, lane = tid & 31, wid = tid >> 5;
    int total = 2 * NN + d_ntask;
    if (blockIdx.x * 8 >= total) return;

    stage_async(w2l, sw, 8192, tid);
    stage_async(w2r, sw + 8192, 8192, tid);
    __pipeline_commit();
    __pipeline_wait_prior(0);
    __syncthreads();

    int c0 = 2 * lane;
    int step = gridDim.x * 8;
    for (int task = blockIdx.x * 8 + wid; task < total; task += step) {
        const float* g;
        const float* W;
        const float* bb;
        float* outp;
        if (task < NN) {
            g = d_g10 + task * 64; W = sw; bb = b2l; outp = d_xl20 + task * 128;
        } else if (task < 2 * NN) {
            int i = task - NN;
            g = d_g1d + (i * DMAX) * 64; W = sw + 8192; bb = b2r; outp = d_xr2 + i * 128;
        } else {
            int v = d_dtasks[task - 2 * NN];
            g = d_g1d + v * 64; W = sw; bb = b2l; outp = d_xl2d + v * 128;
        }
        float a0 = bb[c0], a1 = bb[c0 + 1];
        float a2 = bb[64 + c0], a3 = bb[64 + c0 + 1];
        #pragma unroll 8
        for (int k = 0; k < 64; k++) {
            float gk = g[k];
            float2 wA = *(const float2*)(W + k * 128 + c0);
            float2 wB = *(const float2*)(W + k * 128 + 64 + c0);
            a0 += gk * wA.x; a1 += gk * wA.y;
            a2 += gk * wB.x; a3 += gk * wB.y;
        }
        *(float2*)(outp + c0)      = make_float2(a0, a1);
        *(float2*)(outp + 64 + c0) = make_float2(a2, a3);
    }
}

// ---------------- KC: layer-2 softmax at i + elu + reconstruction ------------
__global__ void __launch_bounds__(64) kC_final(
    const float* __restrict__ att2, const float* __restrict__ bias2,
    const float* __restrict__ recw, const float* __restrict__ recb,
    float* __restrict__ out)
{
    __shared__ __align__(16) float buf[WROWS + 128];
    __shared__ __align__(16) float satt[128];
    __shared__ __align__(16) float hC[128];
    __shared__ __align__(16) float g2s[64];
    __shared__ int sdl[DMAX];
    __shared__ int sedge[64];
    __shared__ int sslot[64];
    __shared__ int snd;

    int i = blockIdx.x;
    int tid = threadIdx.x, lane = tid & 31, h = tid >> 5;
    int hoff = h * 64;
    int c0 = 2 * lane;

    if (tid == 0) snd = d_nd[i];
    if (tid < DMAX) sdl[tid] = d_dlist[i * DMAX + tid];
    satt[tid] = att2[tid];
    satt[64 + tid] = att2[64 + tid];
    __syncthreads();
    int nd = snd;
    int b = d_rowptr[i], deg = d_rowptr[i + 1] - b;

    if (tid < deg) {
        int s = d_csrc[b + tid];
        int sl = -1;
        for (int k = 0; k < nd; k++) if (sdl[k] == s) { sl = k; break; }
        sedge[tid] = s; sslot[tid] = sl;
    }
    __syncthreads();

    for (int j = h; j < deg; j += 2) {
        int s = sedge[j], sl = sslot[j];
        const float* src = (sl >= 0) ? (d_xl2d + (i * DMAX + sl) * 128)
                                     : (d_xl20 + s * 128);
        __pipeline_memcpy_async(buf + j * RSTRIDE + c0,      src + c0,      8);
        __pipeline_memcpy_async(buf + j * RSTRIDE + 64 + c0, src + 64 + c0, 8);
    }
    {
        const float* xr = d_xr2 + i * 128;
        __pipeline_memcpy_async(buf + 64 * RSTRIDE + hoff + c0, xr + hoff + c0, 8);
    }
    __pipeline_commit();
    __pipeline_wait_prior(0);
    __syncthreads();

    float2 o = gat_head_smem(buf, deg, satt, hoff, lane, buf + WROWS + h * 64);
    hC[hoff + c0] = o.x; hC[hoff + c0 + 1] = o.y;
    __syncthreads();
    {
        float v = 0.5f * (hC[tid] + hC[64 + tid]) + bias2[tid];
        g2s[tid] = v > 0.f ? v : expm1f(v);
    }
    __syncthreads();
    {
        float a = recb[tid];
        #pragma unroll 8
        for (int c = 0; c < 64; c++) a += g2s[c] * recw[c * 64 + tid];
        out[i * 64 + tid] = tanhf(a);
    }
}

// ---------------- launch ----------------
extern "C" void kernel_launch(void* const* d_in, const int* in_sizes, int n_in,
                              void* d_out, int out_size)
{
    const float* x          = (const float*)d_in[0];
    const float* E_emb      = (const float*)d_in[1];
    const int*   edge_index = (const int*)  d_in[2];
    const float* node_proj  = (const float*)d_in[3];
    const float* emb_proj   = (const float*)d_in[4];
    const float* conv_w0    = (const float*)d_in[5];
    const float* conv_w1    = (const float*)d_in[6];
    const float* conv_b     = (const float*)d_in[7];
    const float* lin2_w     = (const float*)d_in[8];
    const float* lin2_b     = (const float*)d_in[9];
    const float* masked_proj= (const float*)d_in[10];
    const float* normal_proj= (const float*)d_in[11];
    const float* g1_wl      = (const float*)d_in[12];
    const float* g1_bl      = (const float*)d_in[13];
    const float* g1_wr      = (const float*)d_in[14];
    const float* g1_br      = (const float*)d_in[15];
    const float* g1_att     = (const float*)d_in[16];
    const float* g1_bias    = (const float*)d_in[17];
    const float* g2_wl      = (const float*)d_in[18];
    const float* g2_bl      = (const float*)d_in[19];
    const float* g2_wr      = (const float*)d_in[20];
    const float* g2_br      = (const float*)d_in[21];
    const float* g2_att     = (const float*)d_in[22];
    const float* g2_bias    = (const float*)d_in[23];
    const float* rec_w      = (const float*)d_in[24];
    const float* rec_b      = (const float*)d_in[25];
    float* out = (float*)d_out;

    int E = in_sizes[2] / 2;

    int kA_smem = (KA_PAIRS * PBUF + 192) * 4;   // ~104 KB -> 2 CTAs/SM
    cudaFuncSetAttribute(k1_precompute, cudaFuncAttributeMaxDynamicSharedMemorySize, 149504);
    cudaFuncSetAttribute(kA_gat1, cudaFuncAttributeMaxDynamicSharedMemorySize, kA_smem);
    cudaFuncSetAttribute(kB_xform, cudaFuncAttributeMaxDynamicSharedMemorySize, 65536);

    k1_precompute<<<NN / 4, 256, 149504>>>(x, E_emb, node_proj, emb_proj,
                                           conv_w0, conv_w1, conv_b,
                                           lin2_w, lin2_b, masked_proj, normal_proj,
                                           g1_wl, g1_bl, g1_wr, g1_br);
    k2_csr<<<1, 1024>>>(edge_index, E);
    kD_dlist<<<NN, 128>>>();
    kA_gat1<<<296, KA_PAIRS * 64, kA_smem>>>(g1_att, g1_bias);
    kB_xform<<<99, 256, 65536>>>(g2_wl, g2_bl, g2_wr, g2_br);
    kC_final<<<NN, 64>>>(g2_att, g2_bias, rec_w, rec_b, out);
}